// round 5
// baseline (speedup 1.0000x reference)
#include <cuda_runtime.h>

#define NB 16
#define NP 65536
#define NT 64
#define GB 16                 /* bins per dimension */
#define NBIN (GB*GB)          /* 256 bins per batch */

// ---- k_match config ----
#define THR_M 256
#define APT 4
#define CHUNK (THR_M*APT)     /* 1024 anchors per block; each warp owns 128 contiguous binned slots */

// ---- k_loss config ----
#define THR_L 256
#define NWARP_L (THR_L/32)

__device__ unsigned long long g_bp[NB*NT];   // packed (u_bits<<32)|~anchor_idx per (b,t)
__device__ unsigned char g_match[NB*NP];     // bit7 = pos, bits0-6 = best truth idx
__device__ double g_acc[3];                  // 0: smoothL1 sum, 1: pos count, 2: CE sum
__device__ int g_cnt[NB*NBIN];               // per-bin histogram
__device__ int g_cur[NB*NBIN];               // per-bin scatter cursor
__device__ unsigned char g_binid[NB*NP];     // bin id per anchor
__device__ int g_ord[NB*NP];                 // anchor original indices in binned order

__global__ void k_init(){
    int i = threadIdx.x;
    if (i < NB*NT) g_bp[i] = 0xFFFFFFFFull;  // u = 0, idx = 0 default
    if (i < 3)     g_acc[i] = 0.0;
#pragma unroll
    for (int k = 0; k < (NB*NBIN)/1024; k++){
        g_cnt[k*1024 + i] = 0;
        g_cur[k*1024 + i] = 0;
    }
}

// histogram anchors into 16x16 spatial bins by center
__global__ __launch_bounds__(256)
void k_bin1(const float4* __restrict__ anchors){
    int i = blockIdx.x*256 + threadIdx.x;    // over NB*NP
    float4 a = anchors[i];
    float cx = (a.x + a.z)*0.5f, cy = (a.y + a.w)*0.5f;
    int bx = min(GB-1, max(0, (int)(cx*(float)GB)));
    int by = min(GB-1, max(0, (int)(cy*(float)GB)));
    int bin = by*GB + bx;
    int b = i >> 16;                          // NP = 65536
    g_binid[i] = (unsigned char)bin;
    atomicAdd(&g_cnt[b*NBIN + bin], 1);
}

// per-block redundant scan of the 256 counts + scatter into binned order
__global__ __launch_bounds__(NBIN)
void k_bin3(){
    __shared__ int s_off[NBIN];
    const int b = blockIdx.y, tid = threadIdx.x;
    int c = g_cnt[b*NBIN + tid];
    s_off[tid] = c;
    __syncthreads();
    for (int off = 1; off < NBIN; off <<= 1){
        int v = (tid >= off) ? s_off[tid - off] : 0;
        __syncthreads();
        s_off[tid] += v;
        __syncthreads();
    }
    s_off[tid] -= c;                          // exclusive offsets
    __syncthreads();
    const int base = blockIdx.x * 1024;
#pragma unroll
    for (int k = 0; k < 4; k++){
        int i = base + k*NBIN + tid;
        int bin = g_binid[b*NP + i];
        int p = s_off[bin] + atomicAdd(&g_cur[b*NBIN + bin], 1);
        g_ord[b*NP + p] = i;
    }
}

__global__ __launch_bounds__(THR_M)
void k_match(const float4* __restrict__ anchors, const float4* __restrict__ targets){
    const int b    = blockIdx.y;
    const int tid  = threadIdx.x;
    const int lane = tid & 31, wid = tid >> 5;
    const int slot0 = blockIdx.x*CHUNK + wid*128 + lane;

    __shared__ float4 s_tr[NT];
    __shared__ float  s_ta[NT];
    __shared__ unsigned long long s_key[NT];   // block-local best (u<<32 | ~idx) per truth
    if (tid < NT){
        float4 t4 = targets[b*NT + tid];
        s_tr[tid]  = t4;
        s_ta[tid]  = (t4.z - t4.x) * (t4.w - t4.y);
        s_key[tid] = g_bp[b*NT + tid];         // seed filter from earlier blocks
    }
    __syncthreads();

    int oi[APT]; float4 A[APT]; float aa[APT];
    float bi[APT], bs[APT]; int bt[APT];
#pragma unroll
    for (int k = 0; k < APT; k++){
        oi[k] = g_ord[b*NP + slot0 + k*32];
        A[k]  = anchors[b*NP + oi[k]];
        aa[k] = (A[k].z - A[k].x) * (A[k].w - A[k].y);
        bi[k] = -1.0f; bs[k] = 1.0f; bt[k] = 0;  // sentinel: t=0 wins by default
    }

    // warp bbox over this warp's 128 spatially-local anchors
    float wx1 = fminf(fminf(A[0].x, A[1].x), fminf(A[2].x, A[3].x));
    float wy1 = fminf(fminf(A[0].y, A[1].y), fminf(A[2].y, A[3].y));
    float wx2 = fmaxf(fmaxf(A[0].z, A[1].z), fmaxf(A[2].z, A[3].z));
    float wy2 = fmaxf(fmaxf(A[0].w, A[1].w), fmaxf(A[2].w, A[3].w));
#pragma unroll
    for (int off = 16; off > 0; off >>= 1){
        wx1 = fminf(wx1, __shfl_xor_sync(0xFFFFFFFFu, wx1, off));
        wy1 = fminf(wy1, __shfl_xor_sync(0xFFFFFFFFu, wy1, off));
        wx2 = fmaxf(wx2, __shfl_xor_sync(0xFFFFFFFFu, wx2, off));
        wy2 = fmaxf(wy2, __shfl_xor_sync(0xFFFFFFFFu, wy2, off));
    }

#pragma unroll 1
    for (int t = 0; t < NT; t++){
        float4 tr = s_tr[t];
        // warp-uniform skip: truth can't overlap any anchor in this warp
        if (tr.x >= wx2 || tr.z <= wx1 || tr.y >= wy2 || tr.w <= wy1) continue;
        float atc = s_ta[t];
        unsigned long long cur = s_key[t];

        float li = 0.0f, ls = 1.0f; unsigned lg = 0;
#pragma unroll
        for (int k = 0; k < APT; k++){
            // inter4 = 4*inter via (w+|w|)(h+|h|): exact 2^k scale, fma-pipe friendly
            float w = fminf(tr.z, A[k].z) - fmaxf(tr.x, A[k].x);
            float h = fminf(tr.w, A[k].w) - fmaxf(tr.y, A[k].y);
            float inter4 = (w + fabsf(w)) * (h + fabsf(h));
            float S      = atc + aa[k];
            // anchor side: best truth (strict > keeps first t)
            if (inter4 * bs[k] > bi[k] * S){ bi[k] = inter4; bs[k] = S; bt[k] = t; }
            // prior side: lane-local best anchor for this truth
            if (inter4 * ls > li * S){ li = inter4; ls = S; lg = (unsigned)oi[k]; }
        }
        // running-best filter: stale reads only admit extra attempts; 2-ulp slack
        // guarantees true winners / exact ties always attempt.
        float ub = __uint_as_float((unsigned)(cur >> 32)) * 0.99999988f;
        if (li > 0.0f && li >= ub * ls){
            float u = __fdividef(li, ls);       // monotone with iou
            unsigned long long key =
                ((unsigned long long)__float_as_uint(u) << 32) | (unsigned long long)(~lg);
            atomicMax(&s_key[t], key);
        }
    }

    // pos: 3*inter >= S  <=>  0.75*inter4 >= S (identical rounding); scatter to orig idx
#pragma unroll
    for (int k = 0; k < APT; k++){
        bool pos = (0.75f * bi[k] >= bs[k]);
        g_match[b*NP + oi[k]] =
            (unsigned char)((pos ? 0x80u : 0u) | (unsigned)bt[k]);
    }

    __syncthreads();
    // one global atomic per (block, truth)
    if (tid < NT){
        unsigned long long key = s_key[tid];
        if (key) atomicMax(&g_bp[b*NT + tid], key);
    }
}

// force-match: per batch, sequentially (last t wins on duplicates, like the torch loop)
__global__ void k_force(){
    int b = threadIdx.x;
    if (b < NB){
#pragma unroll 1
        for (int t = 0; t < NT; t++){
            unsigned idx = ~((unsigned)(g_bp[b*NT + t] & 0xFFFFFFFFull));
            g_match[b*NP + idx] = (unsigned char)(0x80u | (unsigned)t);
        }
    }
}

__global__ __launch_bounds__(THR_L)
void k_loss(const float4* __restrict__ loc, const float4* __restrict__ conf4,
            const float4* __restrict__ anchors, const float4* __restrict__ targets){
    const int b    = blockIdx.y;
    const int tid  = threadIdx.x;
    const int base = blockIdx.x * (THR_L*4) + tid*4;

    __shared__ float4 s_tr[NT];
    if (tid < NT) s_tr[tid] = targets[b*NT + tid];
    __syncthreads();

    unsigned mu = *(const unsigned*)&g_match[b*NP + base];
    float4 c01 = conf4[(b*NP + base)/2 + 0];
    float4 c23 = conf4[(b*NP + base)/2 + 1];

    float sl = 0.0f, ce = 0.0f, cnt = 0.0f;
#pragma unroll
    for (int i = 0; i < 4; i++){
        unsigned m = (mu >> (8*i)) & 0xFFu;
        float x0, x1;
        if (i == 0){ x0 = c01.x; x1 = c01.y; }
        else if (i == 1){ x0 = c01.z; x1 = c01.w; }
        else if (i == 2){ x0 = c23.x; x1 = c23.y; }
        else { x0 = c23.z; x1 = c23.w; }
        // ce = logsumexp - x_label; softplus tail: 1 MUFU + deg-4 log1p poly
        // (CE weight in final loss ~1.4e-5 => poly error ~2e-6 relative on output)
        float mx = fmaxf(x0, x1), mn = fminf(x0, x1);
        float y  = __expf(mn - mx);
        float l1p = y*(1.0f - y*(0.5f - y*(0.33333333f - y*0.25f)));
        float xl  = (m & 0x80u) ? x1 : x0;
        ce += (mx - xl) + l1p;

        if (m & 0x80u){   // positive: encode + smooth-L1
            int p = base + i;
            float4 a  = anchors[b*NP + p];
            float4 l  = loc[b*NP + p];
            float4 tr = s_tr[m & 0x7Fu];
            float aw  = a.z - a.x,  ah  = a.w - a.y;
            float acx = (a.x + a.z)*0.5f, acy = (a.y + a.w)*0.5f;
            float mw  = tr.z - tr.x, mh = tr.w - tr.y;
            float mcx = (tr.x + tr.z)*0.5f, mcy = (tr.y + tr.w)*0.5f;
            float rw  = __fdividef(1.0f, aw), rh = __fdividef(1.0f, ah);
            float g0 = (mcx - acx) * rw * 10.0f;
            float g1 = (mcy - acy) * rh * 10.0f;
            float g2 = __logf(mw * rw) * 5.0f;
            float g3 = __logf(mh * rh) * 5.0f;
            float d0 = fabsf(l.x - g0), d1 = fabsf(l.y - g1);
            float d2 = fabsf(l.z - g2), d3 = fabsf(l.w - g3);
            sl += (d0 < 1.0f ? 0.5f*d0*d0 : d0 - 0.5f);
            sl += (d1 < 1.0f ? 0.5f*d1*d1 : d1 - 0.5f);
            sl += (d2 < 1.0f ? 0.5f*d2*d2 : d2 - 0.5f);
            sl += (d3 < 1.0f ? 0.5f*d3*d3 : d3 - 0.5f);
            cnt += 1.0f;
        }
    }

#pragma unroll
    for (int off = 16; off > 0; off >>= 1){
        sl  += __shfl_down_sync(0xFFFFFFFFu, sl,  off);
        ce  += __shfl_down_sync(0xFFFFFFFFu, ce,  off);
        cnt += __shfl_down_sync(0xFFFFFFFFu, cnt, off);
    }
    __shared__ float r0[NWARP_L], r1[NWARP_L], r2[NWARP_L];
    int lane = tid & 31, wid = tid >> 5;
    if (lane == 0){ r0[wid] = sl; r1[wid] = ce; r2[wid] = cnt; }
    __syncthreads();
    if (tid == 0){
        float a = 0.f, c = 0.f, n = 0.f;
#pragma unroll
        for (int w = 0; w < NWARP_L; w++){ a += r0[w]; c += r1[w]; n += r2[w]; }
        atomicAdd(&g_acc[0], (double)a);
        atomicAdd(&g_acc[1], (double)n);
        atomicAdd(&g_acc[2], (double)c);
    }
}

__global__ void k_fin(float* out){
    double loss = g_acc[0] / g_acc[1]
                + g_acc[2] / ((double)NP * (double)NB * (double)NP);
    out[0] = (float)loss;
}

extern "C" void kernel_launch(void* const* d_in, const int* in_sizes, int n_in,
                              void* d_out, int out_size){
    const float4* loc     = (const float4*)d_in[0];
    const float4* conf4   = (const float4*)d_in[1];
    const float4* anchors = (const float4*)d_in[2];
    const float4* targets = (const float4*)d_in[3];
    float* out = (float*)d_out;

    k_init<<<1, 1024>>>();                                      // #1
    k_bin1<<<(NB*NP)/256, 256>>>(anchors);                      // #2
    k_bin3<<<dim3(NP/1024, NB), NBIN>>>();                      // #3
    k_match<<<dim3(NP/CHUNK, NB), THR_M>>>(anchors, targets);   // #4 -> ncu slot
    k_force<<<1, 32>>>();                                       // #5
    k_loss<<<dim3(NP/(THR_L*4), NB), THR_L>>>(loc, conf4, anchors, targets);
    k_fin<<<1, 1>>>(out);
}

// round 6
// speedup vs baseline: 1.7996x; 1.7996x over previous
#include <cuda_runtime.h>

#define NB 16
#define NP 65536
#define NT 64
#define GB 16                 /* bins per dimension */
#define NBIN (GB*GB)          /* 256 bins per batch */
#define BBLK 16               /* binning blocks per batch */
#define APB (NP/BBLK)         /* 4096 anchors per binning block */

// ---- k_match config ----
#define THR_M 256
#define APT 4
#define CHUNK (THR_M*APT)     /* 1024 anchors per block; each warp owns 128 binned slots */

// ---- k_loss config ----
#define THR_L 256
#define NWARP_L (THR_L/32)

__device__ unsigned long long g_bp[NB*NT];   // packed (u_bits<<32)|~anchor_idx per (b,t)
__device__ unsigned char g_match[NB*NP];     // bit7 = pos, bits0-6 = best truth idx
__device__ double g_acc[3];                  // 0: smoothL1 sum, 1: pos count, 2: CE sum
__device__ unsigned g_binrank[NB*NP];        // (bin<<16) | rank-within-(block,bin)
__device__ int g_bcnt[NB*NBIN*BBLK];         // per-(batch,bin,block) counts
__device__ int g_ord[NB*NP];                 // anchor original indices in binned order

__global__ void k_init(){
    int i = threadIdx.x;
    if (i < NB*NT) g_bp[i] = 0xFFFFFFFFull;  // u = 0, idx = 0 default
    if (i < 3)     g_acc[i] = 0.0;
}

// shared-memory histogram: zero global atomics; rank via smem atomicAdd return
__global__ __launch_bounds__(256)
void k_hist(const float4* __restrict__ anchors){
    __shared__ int s_cnt[NBIN];
    const int b = blockIdx.y, blk = blockIdx.x, tid = threadIdx.x;
    for (int i = tid; i < NBIN; i += 256) s_cnt[i] = 0;
    __syncthreads();
    const int base = blk*APB;
#pragma unroll
    for (int k = 0; k < APB/256; k++){
        int i = base + k*256 + tid;
        float4 a = anchors[b*NP + i];
        float cx = (a.x + a.z)*0.5f, cy = (a.y + a.w)*0.5f;
        int bx = min(GB-1, max(0, (int)(cx*(float)GB)));
        int by = min(GB-1, max(0, (int)(cy*(float)GB)));
        int bin = by*GB + bx;
        int r = atomicAdd(&s_cnt[bin], 1);
        g_binrank[b*NP + i] = ((unsigned)bin << 16) | (unsigned)r;
    }
    __syncthreads();
    for (int i = tid; i < NBIN; i += 256)
        g_bcnt[(b*NBIN + i)*BBLK + blk] = s_cnt[i];
}

// per-block redundant scan (16 KB of counts, L2-resident) + contention-free scatter
__global__ __launch_bounds__(NBIN)
void k_scatter(){
    __shared__ int s_tot[NBIN];
    __shared__ int s_base[NBIN];
    const int b = blockIdx.y, blk = blockIdx.x, tid = threadIdx.x;

    // thread tid owns bin tid: total over blocks + prefix over blocks < blk
    int myblkpref = 0, tot = 0;
#pragma unroll
    for (int k = 0; k < BBLK; k++){
        int c = g_bcnt[(b*NBIN + tid)*BBLK + k];
        if (k < blk) myblkpref += c;
        tot += c;
    }
    s_tot[tid] = tot;
    __syncthreads();
    // inclusive scan over bins (read-all-then-write ladder)
    for (int off = 1; off < NBIN; off <<= 1){
        int v = (tid >= off) ? s_tot[tid - off] : 0;
        __syncthreads();
        s_tot[tid] += v;
        __syncthreads();
    }
    s_base[tid] = (s_tot[tid] - tot) + myblkpref;   // exclusive bin base + block prefix
    __syncthreads();

    const int base = blk*APB;
#pragma unroll
    for (int k = 0; k < APB/NBIN; k++){
        int i = base + k*NBIN + tid;
        unsigned pr = g_binrank[b*NP + i];
        int bin = pr >> 16, r = pr & 0xFFFFu;
        g_ord[b*NP + s_base[bin] + r] = i;
    }
}

__global__ __launch_bounds__(THR_M)
void k_match(const float4* __restrict__ anchors, const float4* __restrict__ targets){
    const int b    = blockIdx.y;
    const int tid  = threadIdx.x;
    const int lane = tid & 31, wid = tid >> 5;
    const int slot0 = blockIdx.x*CHUNK + wid*128 + lane;

    __shared__ float4 s_tr[NT];
    __shared__ float  s_ta[NT];
    __shared__ unsigned long long s_key[NT];   // block-local best (u<<32 | ~idx) per truth
    if (tid < NT){
        float4 t4 = targets[b*NT + tid];
        s_tr[tid]  = t4;
        s_ta[tid]  = (t4.z - t4.x) * (t4.w - t4.y);
        s_key[tid] = g_bp[b*NT + tid];         // seed filter from earlier blocks
    }
    __syncthreads();

    int oi[APT]; float4 A[APT]; float aa[APT];
    float bi[APT], bs[APT]; int bt[APT];
#pragma unroll
    for (int k = 0; k < APT; k++){
        oi[k] = g_ord[b*NP + slot0 + k*32];
        A[k]  = anchors[b*NP + oi[k]];
        aa[k] = (A[k].z - A[k].x) * (A[k].w - A[k].y);
        bi[k] = -1.0f; bs[k] = 1.0f; bt[k] = 0;  // sentinel: t=0 wins by default
    }

    // warp bbox over this warp's 128 spatially-local anchors
    float wx1 = fminf(fminf(A[0].x, A[1].x), fminf(A[2].x, A[3].x));
    float wy1 = fminf(fminf(A[0].y, A[1].y), fminf(A[2].y, A[3].y));
    float wx2 = fmaxf(fmaxf(A[0].z, A[1].z), fmaxf(A[2].z, A[3].z));
    float wy2 = fmaxf(fmaxf(A[0].w, A[1].w), fmaxf(A[2].w, A[3].w));
#pragma unroll
    for (int off = 16; off > 0; off >>= 1){
        wx1 = fminf(wx1, __shfl_xor_sync(0xFFFFFFFFu, wx1, off));
        wy1 = fminf(wy1, __shfl_xor_sync(0xFFFFFFFFu, wy1, off));
        wx2 = fmaxf(wx2, __shfl_xor_sync(0xFFFFFFFFu, wx2, off));
        wy2 = fmaxf(wy2, __shfl_xor_sync(0xFFFFFFFFu, wy2, off));
    }

#pragma unroll 1
    for (int t = 0; t < NT; t++){
        float4 tr = s_tr[t];
        // warp-uniform skip: truth can't overlap any anchor in this warp
        if (tr.x >= wx2 || tr.z <= wx1 || tr.y >= wy2 || tr.w <= wy1) continue;
        float atc = s_ta[t];
        unsigned long long cur = s_key[t];

        float li = 0.0f, ls = 1.0f; unsigned lg = 0;
#pragma unroll
        for (int k = 0; k < APT; k++){
            // inter4 = 4*inter via (w+|w|)(h+|h|): exact 2^k scale, fma-pipe friendly
            float w = fminf(tr.z, A[k].z) - fmaxf(tr.x, A[k].x);
            float h = fminf(tr.w, A[k].w) - fmaxf(tr.y, A[k].y);
            float inter4 = (w + fabsf(w)) * (h + fabsf(h));
            float S      = atc + aa[k];
            // anchor side: best truth (strict > keeps first t)
            if (inter4 * bs[k] > bi[k] * S){ bi[k] = inter4; bs[k] = S; bt[k] = t; }
            // prior side: lane-local best anchor for this truth
            if (inter4 * ls > li * S){ li = inter4; ls = S; lg = (unsigned)oi[k]; }
        }
        // running-best filter: stale reads only admit extra attempts; 2-ulp slack
        // guarantees true winners / exact ties always attempt.
        float ub = __uint_as_float((unsigned)(cur >> 32)) * 0.99999988f;
        if (li > 0.0f && li >= ub * ls){
            float u = __fdividef(li, ls);       // monotone with iou
            unsigned long long key =
                ((unsigned long long)__float_as_uint(u) << 32) | (unsigned long long)(~lg);
            atomicMax(&s_key[t], key);
        }
    }

    // pos: 3*inter >= S  <=>  0.75*inter4 >= S (identical rounding); scatter to orig idx
#pragma unroll
    for (int k = 0; k < APT; k++){
        bool pos = (0.75f * bi[k] >= bs[k]);
        g_match[b*NP + oi[k]] =
            (unsigned char)((pos ? 0x80u : 0u) | (unsigned)bt[k]);
    }

    __syncthreads();
    // one global atomic per (block, truth)
    if (tid < NT){
        unsigned long long key = s_key[tid];
        if (key) atomicMax(&g_bp[b*NT + tid], key);
    }
}

// force-match: per batch, sequentially (last t wins on duplicates, like the torch loop)
__global__ void k_force(){
    int b = threadIdx.x;
    if (b < NB){
#pragma unroll 1
        for (int t = 0; t < NT; t++){
            unsigned idx = ~((unsigned)(g_bp[b*NT + t] & 0xFFFFFFFFull));
            g_match[b*NP + idx] = (unsigned char)(0x80u | (unsigned)t);
        }
    }
}

__global__ __launch_bounds__(THR_L)
void k_loss(const float4* __restrict__ loc, const float4* __restrict__ conf4,
            const float4* __restrict__ anchors, const float4* __restrict__ targets){
    const int b    = blockIdx.y;
    const int tid  = threadIdx.x;
    const int base = blockIdx.x * (THR_L*4) + tid*4;

    __shared__ float4 s_tr[NT];
    if (tid < NT) s_tr[tid] = targets[b*NT + tid];
    __syncthreads();

    unsigned mu = *(const unsigned*)&g_match[b*NP + base];
    float4 c01 = conf4[(b*NP + base)/2 + 0];
    float4 c23 = conf4[(b*NP + base)/2 + 1];

    float sl = 0.0f, ce = 0.0f, cnt = 0.0f;
#pragma unroll
    for (int i = 0; i < 4; i++){
        unsigned m = (mu >> (8*i)) & 0xFFu;
        float x0, x1;
        if (i == 0){ x0 = c01.x; x1 = c01.y; }
        else if (i == 1){ x0 = c01.z; x1 = c01.w; }
        else if (i == 2){ x0 = c23.x; x1 = c23.y; }
        else { x0 = c23.z; x1 = c23.w; }
        // ce = logsumexp - x_label; softplus tail: 1 MUFU + deg-4 log1p poly
        // (CE weight in final loss ~1.4e-5 => poly error ~2e-6 relative on output)
        float mx = fmaxf(x0, x1), mn = fminf(x0, x1);
        float y  = __expf(mn - mx);
        float l1p = y*(1.0f - y*(0.5f - y*(0.33333333f - y*0.25f)));
        float xl  = (m & 0x80u) ? x1 : x0;
        ce += (mx - xl) + l1p;

        if (m & 0x80u){   // positive: encode + smooth-L1
            int p = base + i;
            float4 a  = anchors[b*NP + p];
            float4 l  = loc[b*NP + p];
            float4 tr = s_tr[m & 0x7Fu];
            float aw  = a.z - a.x,  ah  = a.w - a.y;
            float acx = (a.x + a.z)*0.5f, acy = (a.y + a.w)*0.5f;
            float mw  = tr.z - tr.x, mh = tr.w - tr.y;
            float mcx = (tr.x + tr.z)*0.5f, mcy = (tr.y + tr.w)*0.5f;
            float rw  = __fdividef(1.0f, aw), rh = __fdividef(1.0f, ah);
            float g0 = (mcx - acx) * rw * 10.0f;
            float g1 = (mcy - acy) * rh * 10.0f;
            float g2 = __logf(mw * rw) * 5.0f;
            float g3 = __logf(mh * rh) * 5.0f;
            float d0 = fabsf(l.x - g0), d1 = fabsf(l.y - g1);
            float d2 = fabsf(l.z - g2), d3 = fabsf(l.w - g3);
            sl += (d0 < 1.0f ? 0.5f*d0*d0 : d0 - 0.5f);
            sl += (d1 < 1.0f ? 0.5f*d1*d1 : d1 - 0.5f);
            sl += (d2 < 1.0f ? 0.5f*d2*d2 : d2 - 0.5f);
            sl += (d3 < 1.0f ? 0.5f*d3*d3 : d3 - 0.5f);
            cnt += 1.0f;
        }
    }

#pragma unroll
    for (int off = 16; off > 0; off >>= 1){
        sl  += __shfl_down_sync(0xFFFFFFFFu, sl,  off);
        ce  += __shfl_down_sync(0xFFFFFFFFu, ce,  off);
        cnt += __shfl_down_sync(0xFFFFFFFFu, cnt, off);
    }
    __shared__ float r0[NWARP_L], r1[NWARP_L], r2[NWARP_L];
    int lane = tid & 31, wid = tid >> 5;
    if (lane == 0){ r0[wid] = sl; r1[wid] = ce; r2[wid] = cnt; }
    __syncthreads();
    if (tid == 0){
        float a = 0.f, c = 0.f, n = 0.f;
#pragma unroll
        for (int w = 0; w < NWARP_L; w++){ a += r0[w]; c += r1[w]; n += r2[w]; }
        atomicAdd(&g_acc[0], (double)a);
        atomicAdd(&g_acc[1], (double)n);
        atomicAdd(&g_acc[2], (double)c);
    }
}

__global__ void k_fin(float* out){
    double loss = g_acc[0] / g_acc[1]
                + g_acc[2] / ((double)NP * (double)NB * (double)NP);
    out[0] = (float)loss;
}

extern "C" void kernel_launch(void* const* d_in, const int* in_sizes, int n_in,
                              void* d_out, int out_size){
    const float4* loc     = (const float4*)d_in[0];
    const float4* conf4   = (const float4*)d_in[1];
    const float4* anchors = (const float4*)d_in[2];
    const float4* targets = (const float4*)d_in[3];
    float* out = (float*)d_out;

    k_init<<<1, 1024>>>();                                      // #1
    k_hist<<<dim3(BBLK, NB), 256>>>(anchors);                   // #2
    k_scatter<<<dim3(BBLK, NB), NBIN>>>();                      // #3
    k_match<<<dim3(NP/CHUNK, NB), THR_M>>>(anchors, targets);   // #4 -> ncu slot
    k_force<<<1, 32>>>();                                       // #5
    k_loss<<<dim3(NP/(THR_L*4), NB), THR_L>>>(loc, conf4, anchors, targets);
    k_fin<<<1, 1>>>(out);
}